// round 1
// baseline (speedup 1.0000x reference)
#include <cuda_runtime.h>

static constexpr int NN = 100000;
static constexpr int D  = 128;
static constexpr int BM = 64;        // GEMM rows per block
static constexpr int WT_LD = 132;    // padded lead dim for transposed W in smem

// Scratch accumulator (allocation-free rule: __device__ global)
__device__ float g_h[(size_t)NN * D];

// ---------------------------------------------------------------------------
// Kernel 1: zero the accumulator
// ---------------------------------------------------------------------------
__global__ void zero_h_kernel() {
    size_t i = (size_t)blockIdx.x * blockDim.x + threadIdx.x;
    size_t n4 = (size_t)NN * D / 4;
    if (i < n4) reinterpret_cast<float4*>(g_h)[i] = make_float4(0.f, 0.f, 0.f, 0.f);
}

// ---------------------------------------------------------------------------
// Kernel 2: per-edge gather * w, scatter-add into g_h via vectorized red.
// One warp per edge: 32 lanes x float4 = 128 floats = one feature row.
// ---------------------------------------------------------------------------
__global__ void scatter_kernel(const float* __restrict__ feat,
                               const int*   __restrict__ src,
                               const int*   __restrict__ dst,
                               const float* __restrict__ ew,
                               int nE) {
    int warp = (blockIdx.x * blockDim.x + threadIdx.x) >> 5;
    int lane = threadIdx.x & 31;
    if (warp >= nE) return;

    int   s = __ldg(src + warp);
    int   d = __ldg(dst + warp);
    float w = __ldg(ew  + warp);

    float4 v = *reinterpret_cast<const float4*>(feat + (size_t)s * D + lane * 4);
    v.x *= w; v.y *= w; v.z *= w; v.w *= w;

    float* p = g_h + (size_t)d * D + lane * 4;
    // sm_90+ vectorized reduction: one L2 atomic transaction per 16B
    asm volatile("red.global.add.v4.f32 [%0], {%1,%2,%3,%4};"
                 :: "l"(p), "f"(v.x), "f"(v.y), "f"(v.z), "f"(v.w)
                 : "memory");
}

// ---------------------------------------------------------------------------
// Kernel 3: y = g_h @ W^T + b   (fp32 SIMT GEMM, K = 128 fully resident)
// Block: 256 threads (8 warps). Tile: BM=64 rows x 128 cols.
// Thread (ty in 0..7, tx in 0..31) computes 8 rows x 4 cols.
// W is [D_OUT][D_IN] row-major; transposed into smem Wt[i][o] (stride 132,
// keeps float4 reads 16B-aligned and conflict-free).
// ---------------------------------------------------------------------------
__global__ void gemm_kernel(const float* __restrict__ W,
                            const float* __restrict__ b,
                            float*       __restrict__ y) {
    extern __shared__ float sm[];
    float* Wt = sm;               // [D][WT_LD]
    float* hs = sm + D * WT_LD;   // [BM][D]

    int tid = threadIdx.x;
    int tx  = tid & 31;
    int ty  = tid >> 5;

    // Stage W transposed: Wt[i*WT_LD + o] = W[o*D + i]
    for (int idx = tid; idx < D * D; idx += 256) {
        int o = idx >> 7, i = idx & 127;
        Wt[i * WT_LD + o] = W[idx];
    }

    // Stage h tile (coalesced float4), zero-pad past NN
    int row0 = blockIdx.x * BM;
    for (int idx = tid * 4; idx < BM * D; idx += 256 * 4) {
        int m   = idx >> 7;
        int row = row0 + m;
        float4 v = (row < NN)
            ? *reinterpret_cast<const float4*>(&g_h[(size_t)row * D + (idx & 127)])
            : make_float4(0.f, 0.f, 0.f, 0.f);
        *reinterpret_cast<float4*>(&hs[idx]) = v;
    }
    __syncthreads();

    float acc[8][4];
    #pragma unroll
    for (int j = 0; j < 8; j++)
        #pragma unroll
        for (int c = 0; c < 4; c++) acc[j][c] = 0.f;

    #pragma unroll 4
    for (int k = 0; k < D; k += 4) {
        float4 wv0 = *reinterpret_cast<const float4*>(&Wt[(k + 0) * WT_LD + tx * 4]);
        float4 wv1 = *reinterpret_cast<const float4*>(&Wt[(k + 1) * WT_LD + tx * 4]);
        float4 wv2 = *reinterpret_cast<const float4*>(&Wt[(k + 2) * WT_LD + tx * 4]);
        float4 wv3 = *reinterpret_cast<const float4*>(&Wt[(k + 3) * WT_LD + tx * 4]);
        #pragma unroll
        for (int j = 0; j < 8; j++) {
            // broadcast LDS.128 (address independent of tx)
            float4 a = *reinterpret_cast<const float4*>(&hs[(ty * 8 + j) * D + k]);
            acc[j][0] += a.x * wv0.x; acc[j][1] += a.x * wv0.y;
            acc[j][2] += a.x * wv0.z; acc[j][3] += a.x * wv0.w;
            acc[j][0] += a.y * wv1.x; acc[j][1] += a.y * wv1.y;
            acc[j][2] += a.y * wv1.z; acc[j][3] += a.y * wv1.w;
            acc[j][0] += a.z * wv2.x; acc[j][1] += a.z * wv2.y;
            acc[j][2] += a.z * wv2.z; acc[j][3] += a.z * wv2.w;
            acc[j][0] += a.w * wv3.x; acc[j][1] += a.w * wv3.y;
            acc[j][2] += a.w * wv3.z; acc[j][3] += a.w * wv3.w;
        }
    }

    float4 bb = *reinterpret_cast<const float4*>(&b[tx * 4]);
    #pragma unroll
    for (int j = 0; j < 8; j++) {
        int row = row0 + ty * 8 + j;
        if (row < NN) {
            float4 o;
            o.x = acc[j][0] + bb.x;
            o.y = acc[j][1] + bb.y;
            o.z = acc[j][2] + bb.z;
            o.w = acc[j][3] + bb.w;
            *reinterpret_cast<float4*>(&y[(size_t)row * D + tx * 4]) = o;
        }
    }
}

// ---------------------------------------------------------------------------
extern "C" void kernel_launch(void* const* d_in, const int* in_sizes, int n_in,
                              void* d_out, int out_size) {
    const float* feat = (const float*)d_in[0];
    const int*   src  = (const int*)  d_in[1];
    const int*   dst  = (const int*)  d_in[2];
    const float* ew   = (const float*)d_in[3];
    const float* W    = (const float*)d_in[4];
    const float* b    = (const float*)d_in[5];
    float*       y    = (float*)d_out;
    int nE = in_sizes[1];

    // 1) zero accumulator
    {
        int n4 = NN * D / 4;
        zero_h_kernel<<<(n4 + 255) / 256, 256>>>();
    }

    // 2) scatter-add (one warp per edge)
    {
        long long total_threads = (long long)nE * 32;
        int blocks = (int)((total_threads + 255) / 256);
        scatter_kernel<<<blocks, 256>>>(feat, src, dst, ew, nE);
    }

    // 3) GEMM + bias
    {
        int smem = (D * WT_LD + BM * D) * (int)sizeof(float);  // ~98KB
        cudaFuncSetAttribute(gemm_kernel,
                             cudaFuncAttributeMaxDynamicSharedMemorySize, smem);
        int blocks = (NN + BM - 1) / BM;
        gemm_kernel<<<blocks, 256, smem>>>(W, b, y);
    }
}

// round 2
// speedup vs baseline: 1.2991x; 1.2991x over previous
#include <cuda_runtime.h>

static constexpr int NN = 100000;
static constexpr int D  = 128;
static constexpr int LDS_PAD = 132;   // smem lead dim (floats), conflict-free

// Scratch accumulator (allocation-free rule: __device__ global)
__device__ float g_h[(size_t)NN * D];

// ---------------------------------------------------------------------------
// Kernel 1: zero the accumulator
// ---------------------------------------------------------------------------
__global__ void zero_h_kernel() {
    size_t i = (size_t)blockIdx.x * blockDim.x + threadIdx.x;
    size_t n4 = (size_t)NN * D / 4;
    if (i < n4) reinterpret_cast<float4*>(g_h)[i] = make_float4(0.f, 0.f, 0.f, 0.f);
}

// ---------------------------------------------------------------------------
// Kernel 2: per-edge gather * w, scatter-add into g_h via vectorized red.
// One warp per edge: 32 lanes x float4 = 128 floats = one feature row.
// ---------------------------------------------------------------------------
__global__ void scatter_kernel(const float* __restrict__ feat,
                               const int*   __restrict__ src,
                               const int*   __restrict__ dst,
                               const float* __restrict__ ew,
                               int nE) {
    int warp = (blockIdx.x * blockDim.x + threadIdx.x) >> 5;
    int lane = threadIdx.x & 31;
    if (warp >= nE) return;

    int   s = __ldg(src + warp);
    int   d = __ldg(dst + warp);
    float w = __ldg(ew  + warp);

    float4 v = *reinterpret_cast<const float4*>(feat + (size_t)s * D + lane * 4);
    v.x *= w; v.y *= w; v.z *= w; v.w *= w;

    float* p = g_h + (size_t)d * D + lane * 4;
    asm volatile("red.global.add.v4.f32 [%0], {%1,%2,%3,%4};"
                 :: "l"(p), "f"(v.x), "f"(v.y), "f"(v.z), "f"(v.w)
                 : "memory");
}

// ---------------------------------------------------------------------------
// Kernel 3: y = g_h @ W^T + b via tf32 mma.sync.m16n8k8
//
// CTA: 128 rows x 128 cols, K=128 fully resident in smem.
// 8 warps arranged 4 (m) x 2 (n): warp tile = 32 rows x 64 cols
//   = 2 m16 tiles x 8 n8 tiles = 16 mma per k-step, 16 k-steps.
// A = h rows (row-major, m16n8k8.row), B = W rows (W is [N][K] row-major,
//   which IS K-col-major => .col operand directly, no transpose).
// tf32 rounding (cvt.rna) applied once at staging.
// ---------------------------------------------------------------------------
__device__ __forceinline__ unsigned f2tf32(float f) {
    unsigned u;
    asm("cvt.rna.tf32.f32 %0, %1;" : "=r"(u) : "f"(f));
    return u;
}

__device__ __forceinline__ void mma_tf32(float* d, const unsigned* a, const unsigned* b) {
    asm volatile(
        "mma.sync.aligned.m16n8k8.row.col.f32.tf32.tf32.f32 "
        "{%0,%1,%2,%3}, {%4,%5,%6,%7}, {%8,%9}, {%0,%1,%2,%3};"
        : "+f"(d[0]), "+f"(d[1]), "+f"(d[2]), "+f"(d[3])
        : "r"(a[0]), "r"(a[1]), "r"(a[2]), "r"(a[3]),
          "r"(b[0]), "r"(b[1]));
}

__global__ void gemm_tf32_kernel(const float* __restrict__ W,
                                 const float* __restrict__ b,
                                 float*       __restrict__ y) {
    extern __shared__ unsigned sm[];
    unsigned* As = sm;                       // [128][LDS_PAD] tf32 of h tile
    unsigned* Bs = sm + D * LDS_PAD;         // [128][LDS_PAD] tf32 of W
    float*    bs = reinterpret_cast<float*>(sm + 2 * D * LDS_PAD);  // [128]

    const int tid  = threadIdx.x;
    const int lane = tid & 31;
    const int wid  = tid >> 5;
    const int wm   = wid & 3;        // 0..3 -> m offset 32*wm
    const int wn   = wid >> 2;       // 0..1 -> n offset 64*wn
    const int g    = lane >> 2;      // 0..7
    const int tg   = lane & 3;       // 0..3

    const int row0 = blockIdx.x * 128;

    // ---- Stage A (h tile, rows row0..row0+127), tf32-rounded ----
    #pragma unroll
    for (int it = 0; it < 16; it++) {
        int idx = tid + it * 256;        // float4 index, 32 per row
        int r   = idx >> 5;
        int c4  = (idx & 31) * 4;
        int row = row0 + r;
        float4 v = (row < NN)
            ? *reinterpret_cast<const float4*>(&g_h[(size_t)row * D + c4])
            : make_float4(0.f, 0.f, 0.f, 0.f);
        unsigned* p = &As[r * LDS_PAD + c4];
        p[0] = f2tf32(v.x); p[1] = f2tf32(v.y);
        p[2] = f2tf32(v.z); p[3] = f2tf32(v.w);
    }
    // ---- Stage B (W, full 128x128), tf32-rounded ----
    #pragma unroll
    for (int it = 0; it < 16; it++) {
        int idx = tid + it * 256;
        int r   = idx >> 5;
        int c4  = (idx & 31) * 4;
        float4 v = *reinterpret_cast<const float4*>(&W[r * D + c4]);
        unsigned* p = &Bs[r * LDS_PAD + c4];
        p[0] = f2tf32(v.x); p[1] = f2tf32(v.y);
        p[2] = f2tf32(v.z); p[3] = f2tf32(v.w);
    }
    if (tid < 128) bs[tid] = b[tid];
    __syncthreads();

    float acc[2][8][4];
    #pragma unroll
    for (int mi = 0; mi < 2; mi++)
        #pragma unroll
        for (int ni = 0; ni < 8; ni++)
            #pragma unroll
            for (int c = 0; c < 4; c++) acc[mi][ni][c] = 0.f;

    const unsigned* Abase = &As[(wm * 32 + g) * LDS_PAD + tg];
    const unsigned* Bbase = &Bs[(wn * 64 + g) * LDS_PAD + tg];

    #pragma unroll 4
    for (int kk = 0; kk < 16; kk++) {
        const int k0 = kk * 8;
        unsigned af[2][4];
        #pragma unroll
        for (int mi = 0; mi < 2; mi++) {
            const unsigned* p = Abase + mi * 16 * LDS_PAD + k0;
            af[mi][0] = p[0];
            af[mi][1] = p[8 * LDS_PAD];
            af[mi][2] = p[4];
            af[mi][3] = p[8 * LDS_PAD + 4];
        }
        unsigned bf[8][2];
        #pragma unroll
        for (int ni = 0; ni < 8; ni++) {
            const unsigned* p = Bbase + ni * 8 * LDS_PAD + k0;
            bf[ni][0] = p[0];
            bf[ni][1] = p[4];
        }
        #pragma unroll
        for (int mi = 0; mi < 2; mi++)
            #pragma unroll
            for (int ni = 0; ni < 8; ni++)
                mma_tf32(acc[mi][ni], af[mi], bf[ni]);
    }

    // ---- Epilogue: add bias, store float2 per (mi, ni, row-half) ----
    #pragma unroll
    for (int mi = 0; mi < 2; mi++) {
        #pragma unroll
        for (int ni = 0; ni < 8; ni++) {
            int col = wn * 64 + ni * 8 + 2 * tg;
            float b0 = bs[col], b1 = bs[col + 1];
            int r_lo = row0 + wm * 32 + mi * 16 + g;
            int r_hi = r_lo + 8;
            if (r_lo < NN) {
                float2 o = make_float2(acc[mi][ni][0] + b0, acc[mi][ni][1] + b1);
                *reinterpret_cast<float2*>(&y[(size_t)r_lo * D + col]) = o;
            }
            if (r_hi < NN) {
                float2 o = make_float2(acc[mi][ni][2] + b0, acc[mi][ni][3] + b1);
                *reinterpret_cast<float2*>(&y[(size_t)r_hi * D + col]) = o;
            }
        }
    }
}

// ---------------------------------------------------------------------------
extern "C" void kernel_launch(void* const* d_in, const int* in_sizes, int n_in,
                              void* d_out, int out_size) {
    const float* feat = (const float*)d_in[0];
    const int*   src  = (const int*)  d_in[1];
    const int*   dst  = (const int*)  d_in[2];
    const float* ew   = (const float*)d_in[3];
    const float* W    = (const float*)d_in[4];
    const float* b    = (const float*)d_in[5];
    float*       y    = (float*)d_out;
    int nE = in_sizes[1];

    // 1) zero accumulator
    {
        int n4 = NN * D / 4;
        zero_h_kernel<<<(n4 + 255) / 256, 256>>>();
    }

    // 2) scatter-add (one warp per edge)
    {
        long long total_threads = (long long)nE * 32;
        int blocks = (int)((total_threads + 255) / 256);
        scatter_kernel<<<blocks, 256>>>(feat, src, dst, ew, nE);
    }

    // 3) tf32 tensor-core GEMM + bias
    {
        int smem = (2 * D * LDS_PAD + D) * (int)sizeof(float);  // ~135.7KB
        cudaFuncSetAttribute(gemm_tf32_kernel,
                             cudaFuncAttributeMaxDynamicSharedMemorySize, smem);
        int blocks = (NN + 127) / 128;   // 782
        gemm_tf32_kernel<<<blocks, 256, smem>>>(W, b, y);
    }
}